// round 10
// baseline (speedup 1.0000x reference)
#include <cuda_runtime.h>
#include <cuda_bf16.h>
#include <cfloat>

#define Bq 4
#define Np 4096
#define Kn 32
#define Jcols (Bq * Np)   // 16384

// ---------------- scratch (device globals; no allocs allowed) ----------------
__device__ int   g_idx[Bq * Np * Kn];            // 2 MB
__device__ float g_P0[384L * Jcols];             // 25 MB   [384][16384]
__device__ float g_G1[256L * Jcols];             // 16 MB
__device__ float g_G2[1024L * Jcols];            // 67 MB
__device__ float g_M1[256L * Jcols];             // 16 MB

// ============================================================================
// Kernel 1: KNN. grid (Np/QPB, B), block 128. Dynamic smem:
//   sx[4096], sy[4096], sz[4096], dist[4096]  = 64 KB
// Each block processes QPB=8 query points sequentially; per query: compute
// all 4096 squared distances into smem, then 32 incremental argmin extractions
// (only the owning thread rescans its 32-entry stride after an extraction).
// ============================================================================
#define QPB 8
__global__ __launch_bounds__(128) void knn_kernel(const float* __restrict__ x,
                                                  int* __restrict__ idx_out) {
    extern __shared__ float sm[];
    float* sx = sm;
    float* sy = sm + Np;
    float* sz = sm + 2 * Np;
    float* dist = sm + 3 * Np;
    __shared__ float red_v[4];
    __shared__ int   red_i[4];
    __shared__ int   s_win;

    const int t = threadIdx.x;
    const int lane = t & 31;
    const int warp = t >> 5;
    const int b = blockIdx.y;

    for (int m = t; m < Np; m += 128) {
        sx[m] = x[(b * 3 + 0) * Np + m];
        sy[m] = x[(b * 3 + 1) * Np + m];
        sz[m] = x[(b * 3 + 2) * Np + m];
    }
    __syncthreads();

    for (int q = 0; q < QPB; q++) {
        const int n = blockIdx.x * QPB + q;
        const float qx = sx[n], qy = sy[n], qz = sz[n];
        for (int m = t; m < Np; m += 128) {
            float dx = sx[m] - qx, dy = sy[m] - qy, dz = sz[m] - qz;
            float d = dx * dx + dy * dy + dz * dz;
            dist[m] = (m == n) ? FLT_MAX : d;
        }
        __syncthreads();

        // local min over my 32-entry stride
        float bestv = FLT_MAX; int besti = t;
        #pragma unroll
        for (int i = 0; i < Np / 128; i++) {
            int m = t + i * 128;
            float v = dist[m];
            if (v < bestv) { bestv = v; besti = m; }
        }

        for (int it = 0; it < Kn; it++) {
            float v = bestv; int bi = besti;
            #pragma unroll
            for (int off = 16; off; off >>= 1) {
                float ov = __shfl_xor_sync(0xffffffffu, v, off);
                int   oi = __shfl_xor_sync(0xffffffffu, bi, off);
                if (ov < v) { v = ov; bi = oi; }
            }
            if (lane == 0) { red_v[warp] = v; red_i[warp] = bi; }
            __syncthreads();
            if (t == 0) {
                float wv = red_v[0]; int wi = red_i[0];
                #pragma unroll
                for (int w = 1; w < 4; w++)
                    if (red_v[w] < wv) { wv = red_v[w]; wi = red_i[w]; }
                s_win = wi;
                idx_out[(b * Np + n) * Kn + it] = wi;
            }
            __syncthreads();
            int win = s_win;
            if ((win & 127) == t) {
                dist[win] = FLT_MAX;
                bestv = FLT_MAX; besti = t;
                #pragma unroll
                for (int i = 0; i < Np / 128; i++) {
                    int m = t + i * 128;
                    float fv = dist[m];
                    if (fv < bestv) { bestv = fv; besti = m; }
                }
            }
            __syncthreads();
        }
        __syncthreads();
    }
}

// ============================================================================
// Kernel 2: fused scale MLP (3 -> 64 -> 64 -> 128, relu) + max over K=32.
// grid (Np/4, B, 3 scales), block 128 (4 warps, each warp = one point,
// lane = neighbor). Weights of this scale staged in smem (50944 B dynamic).
// Output: g_P0[(s*128+o)][b*Np+n].
// ============================================================================
__global__ __launch_bounds__(128) void scale_mlp_kernel(
    const float* __restrict__ x, const int* __restrict__ idx,
    float* __restrict__ P0,
    const float* __restrict__ sW0, const float* __restrict__ sb0,
    const float* __restrict__ sW1, const float* __restrict__ sb1,
    const float* __restrict__ sW2, const float* __restrict__ sb2) {
    extern __shared__ float sm[];
    float* w0 = sm;               // 192
    float* b0 = sm + 192;         // 64
    float* w1 = sm + 256;         // 4096
    float* b1 = sm + 4352;        // 64
    float* w2 = sm + 4416;        // 8192
    float* b2 = sm + 12608;       // 128  (total 12736 floats)

    const int t = threadIdx.x;
    const int s = blockIdx.z;
    for (int i = t; i < 192; i += 128)  w0[i] = sW0[s * 192 + i];
    for (int i = t; i < 64;  i += 128)  b0[i] = sb0[s * 64 + i];
    for (int i = t; i < 4096; i += 128) w1[i] = sW1[s * 4096 + i];
    for (int i = t; i < 64;  i += 128)  b1[i] = sb1[s * 64 + i];
    for (int i = t; i < 8192; i += 128) w2[i] = sW2[s * 8192 + i];
    for (int i = t; i < 128; i += 128)  b2[i] = sb2[s * 128 + i];
    __syncthreads();

    const int lane = t & 31;
    const int warp = t >> 5;
    const int n = blockIdx.x * 4 + warp;
    const int b = blockIdx.y;

    const int j = idx[(b * Np + n) * Kn + lane];
    const float px = x[(b * 3 + 0) * Np + j];
    const float py = x[(b * 3 + 1) * Np + j];
    const float pz = x[(b * 3 + 2) * Np + j];

    float h0[64];
    #pragma unroll
    for (int o = 0; o < 64; o++) {
        float a = b0[o];
        a = fmaf(w0[o * 3 + 0], px, a);
        a = fmaf(w0[o * 3 + 1], py, a);
        a = fmaf(w0[o * 3 + 2], pz, a);
        h0[o] = fmaxf(a, 0.0f);
    }

    float h1[64];
    #pragma unroll
    for (int o = 0; o < 64; o++) {
        float a = b1[o];
        const float4* wr = (const float4*)&w1[o * 64];
        #pragma unroll
        for (int c = 0; c < 16; c++) {
            float4 wv = wr[c];
            a = fmaf(wv.x, h0[4 * c + 0], a);
            a = fmaf(wv.y, h0[4 * c + 1], a);
            a = fmaf(wv.z, h0[4 * c + 2], a);
            a = fmaf(wv.w, h0[4 * c + 3], a);
        }
        h1[o] = fmaxf(a, 0.0f);
    }

    for (int o = 0; o < 128; o++) {
        float a = b2[o];
        const float4* wr = (const float4*)&w2[o * 64];
        #pragma unroll
        for (int c = 0; c < 16; c++) {
            float4 wv = wr[c];
            a = fmaf(wv.x, h1[4 * c + 0], a);
            a = fmaf(wv.y, h1[4 * c + 1], a);
            a = fmaf(wv.z, h1[4 * c + 2], a);
            a = fmaf(wv.w, h1[4 * c + 3], a);
        }
        a = fmaxf(a, 0.0f);
        #pragma unroll
        for (int off = 16; off; off >>= 1)
            a = fmaxf(a, __shfl_xor_sync(0xffffffffu, a, off));
        if (lane == 0)
            P0[(s * 128 + o) * Jcols + b * Np + n] = a;
    }
}

// ============================================================================
// Kernel 3: generic SGEMM  Y[O][J] = relu(W[O][Cin] * X[Cin][J] + bias).
// Tile 64x64, BK=16, 256 threads, 4x4 microtile.
// mode 0: Y row-major [O][J].  mode 1: msf output -> Y[((j>>12)*128+o)*4096+(j&4095)].
// ============================================================================
__global__ __launch_bounds__(256) void gemm_relu_kernel(
    const float* __restrict__ W, const float* __restrict__ Bv,
    const float* __restrict__ X, float* __restrict__ Y,
    int O, int Cin, int mode) {
    __shared__ float Ws[16][64];
    __shared__ float Xs[16][64];
    const int t = threadIdx.x;
    const int o0 = blockIdx.y * 64, j0 = blockIdx.x * 64;

    const int lo = t >> 2, lq = t & 3;     // W tile load
    const int lk = t >> 4, lj = t & 15;    // X tile load
    const int to = (t >> 4) << 2, tj = (t & 15) << 2;

    float acc[4][4];
    #pragma unroll
    for (int i = 0; i < 4; i++)
        #pragma unroll
        for (int jj = 0; jj < 4; jj++) acc[i][jj] = 0.0f;

    for (int k0 = 0; k0 < Cin; k0 += 16) {
        float4 wv = *(const float4*)&W[(o0 + lo) * Cin + k0 + lq * 4];
        Ws[lq * 4 + 0][lo] = wv.x;
        Ws[lq * 4 + 1][lo] = wv.y;
        Ws[lq * 4 + 2][lo] = wv.z;
        Ws[lq * 4 + 3][lo] = wv.w;
        *(float4*)&Xs[lk][lj * 4] = *(const float4*)&X[(k0 + lk) * Jcols + j0 + lj * 4];
        __syncthreads();
        #pragma unroll
        for (int kk = 0; kk < 16; kk++) {
            float4 a = *(const float4*)&Ws[kk][to];
            float4 xv = *(const float4*)&Xs[kk][tj];
            acc[0][0] = fmaf(a.x, xv.x, acc[0][0]);
            acc[0][1] = fmaf(a.x, xv.y, acc[0][1]);
            acc[0][2] = fmaf(a.x, xv.z, acc[0][2]);
            acc[0][3] = fmaf(a.x, xv.w, acc[0][3]);
            acc[1][0] = fmaf(a.y, xv.x, acc[1][0]);
            acc[1][1] = fmaf(a.y, xv.y, acc[1][1]);
            acc[1][2] = fmaf(a.y, xv.z, acc[1][2]);
            acc[1][3] = fmaf(a.y, xv.w, acc[1][3]);
            acc[2][0] = fmaf(a.z, xv.x, acc[2][0]);
            acc[2][1] = fmaf(a.z, xv.y, acc[2][1]);
            acc[2][2] = fmaf(a.z, xv.z, acc[2][2]);
            acc[2][3] = fmaf(a.z, xv.w, acc[2][3]);
            acc[3][0] = fmaf(a.w, xv.x, acc[3][0]);
            acc[3][1] = fmaf(a.w, xv.y, acc[3][1]);
            acc[3][2] = fmaf(a.w, xv.z, acc[3][2]);
            acc[3][3] = fmaf(a.w, xv.w, acc[3][3]);
        }
        __syncthreads();
    }

    #pragma unroll
    for (int i = 0; i < 4; i++) {
        const int o = o0 + to + i;
        const float bi = Bv[o];
        #pragma unroll
        for (int jj = 0; jj < 4; jj++) {
            const int j = j0 + tj + jj;
            float v = fmaxf(acc[i][jj] + bi, 0.0f);
            if (mode == 0)
                Y[o * Jcols + j] = v;
            else
                Y[((j >> 12) * 128 + o) * Np + (j & (Np - 1))] = v;
        }
    }
}

// ============================================================================
// Kernel 4: global_feature[b][o] = max_n G2[o][b*Np+n].  One warp per (b,o).
// ============================================================================
__global__ __launch_bounds__(256) void gfmax_kernel(const float* __restrict__ G2,
                                                    float* __restrict__ out) {
    const int w = (blockIdx.x * blockDim.x + threadIdx.x) >> 5;
    const int lane = threadIdx.x & 31;
    const int b = w >> 10, o = w & 1023;
    const float* row = &G2[o * Jcols + b * Np];
    float m = 0.0f;  // relu outputs are >= 0
    for (int i = lane; i < Np; i += 32) m = fmaxf(m, row[i]);
    #pragma unroll
    for (int off = 16; off; off >>= 1)
        m = fmaxf(m, __shfl_xor_sync(0xffffffffu, m, off));
    if (lane == 0) out[b * 1024 + o] = m;
}

// ============================================================================
extern "C" void kernel_launch(void* const* d_in, const int* in_sizes, int n_in,
                              void* d_out, int out_size) {
    const float* x   = (const float*)d_in[0];
    const float* sW0 = (const float*)d_in[1];
    const float* sb0 = (const float*)d_in[2];
    const float* sW1 = (const float*)d_in[3];
    const float* sb1 = (const float*)d_in[4];
    const float* sW2 = (const float*)d_in[5];
    const float* sb2 = (const float*)d_in[6];
    const float* gW0 = (const float*)d_in[7];
    const float* gb0 = (const float*)d_in[8];
    const float* gW1 = (const float*)d_in[9];
    const float* gb1 = (const float*)d_in[10];
    const float* mW0 = (const float*)d_in[11];
    const float* mb0 = (const float*)d_in[12];
    const float* mW1 = (const float*)d_in[13];
    const float* mb1 = (const float*)d_in[14];
    float* out = (float*)d_out;

    int*   IDX; float *P0, *G1, *G2, *M1;
    cudaGetSymbolAddress((void**)&IDX, g_idx);
    cudaGetSymbolAddress((void**)&P0, g_P0);
    cudaGetSymbolAddress((void**)&G1, g_G1);
    cudaGetSymbolAddress((void**)&G2, g_G2);
    cudaGetSymbolAddress((void**)&M1, g_M1);

    const int knn_smem = 4 * Np * sizeof(float);           // 64 KB
    const int mlp_smem = 12736 * sizeof(float);            // ~50 KB
    cudaFuncSetAttribute(knn_kernel, cudaFuncAttributeMaxDynamicSharedMemorySize, knn_smem);
    cudaFuncSetAttribute(scale_mlp_kernel, cudaFuncAttributeMaxDynamicSharedMemorySize, mlp_smem);

    // 1) KNN
    knn_kernel<<<dim3(Np / QPB, Bq), 128, knn_smem>>>(x, IDX);

    // 2) per-scale MLP + max over neighbors -> P0 [384][16384]
    scale_mlp_kernel<<<dim3(Np / 4, Bq, 3), 128, mlp_smem>>>(
        x, IDX, P0, sW0, sb0, sW1, sb1, sW2, sb2);

    // 3) dense chain
    gemm_relu_kernel<<<dim3(Jcols / 64, 256 / 64), 256>>>(gW0, gb0, P0, G1, 256, 384, 0);
    gemm_relu_kernel<<<dim3(Jcols / 64, 1024 / 64), 256>>>(gW1, gb1, G1, G2, 1024, 256, 0);

    // 4) global feature = max over N of G2 -> out[0 .. 4096)
    gfmax_kernel<<<512, 256>>>(G2, out);

    // 5) msf chain
    gemm_relu_kernel<<<dim3(Jcols / 64, 256 / 64), 256>>>(mW0, mb0, G2, M1, 256, 1024, 0);
    gemm_relu_kernel<<<dim3(Jcols / 64, 128 / 64), 256>>>(mW1, mb1, M1, out + Bq * 1024, 128, 256, 1);
}

// round 12
// speedup vs baseline: 2.4616x; 2.4616x over previous
#include <cuda_runtime.h>
#include <cuda_bf16.h>
#include <cfloat>

#define Bq 4
#define Np 4096
#define Kn 32
#define Jcols (Bq * Np)   // 16384

// ---------------- scratch (device globals; no allocs allowed) ----------------
__device__ int   g_idx[Bq * Np * Kn];            // 2 MB
__device__ float g_F [(size_t)Jcols * 384];      // 25 MB   point-major [16384][384]
__device__ float g_P0[384L * Jcols];             // 25 MB   [384][16384]
__device__ float g_G1[256L * Jcols];             // 16 MB
__device__ float g_G2[1024L * Jcols];            // 67 MB
__device__ float g_M1[256L * Jcols];             // 16 MB

// ============================================================================
// Kernel 1: KNN (unchanged). grid (Np/QPB, B), block 128.
// ============================================================================
#define QPB 8
__global__ __launch_bounds__(128) void knn_kernel(const float* __restrict__ x,
                                                  int* __restrict__ idx_out) {
    extern __shared__ float sm[];
    float* sx = sm;
    float* sy = sm + Np;
    float* sz = sm + 2 * Np;
    float* dist = sm + 3 * Np;
    __shared__ float red_v[4];
    __shared__ int   red_i[4];
    __shared__ int   s_win;

    const int t = threadIdx.x;
    const int lane = t & 31;
    const int warp = t >> 5;
    const int b = blockIdx.y;

    for (int m = t; m < Np; m += 128) {
        sx[m] = x[(b * 3 + 0) * Np + m];
        sy[m] = x[(b * 3 + 1) * Np + m];
        sz[m] = x[(b * 3 + 2) * Np + m];
    }
    __syncthreads();

    for (int q = 0; q < QPB; q++) {
        const int n = blockIdx.x * QPB + q;
        const float qx = sx[n], qy = sy[n], qz = sz[n];
        for (int m = t; m < Np; m += 128) {
            float dx = sx[m] - qx, dy = sy[m] - qy, dz = sz[m] - qz;
            float d = dx * dx + dy * dy + dz * dz;
            dist[m] = (m == n) ? FLT_MAX : d;
        }
        __syncthreads();

        float bestv = FLT_MAX; int besti = t;
        #pragma unroll
        for (int i = 0; i < Np / 128; i++) {
            int m = t + i * 128;
            float v = dist[m];
            if (v < bestv) { bestv = v; besti = m; }
        }

        for (int it = 0; it < Kn; it++) {
            float v = bestv; int bi = besti;
            #pragma unroll
            for (int off = 16; off; off >>= 1) {
                float ov = __shfl_xor_sync(0xffffffffu, v, off);
                int   oi = __shfl_xor_sync(0xffffffffu, bi, off);
                if (ov < v) { v = ov; bi = oi; }
            }
            if (lane == 0) { red_v[warp] = v; red_i[warp] = bi; }
            __syncthreads();
            if (t == 0) {
                float wv = red_v[0]; int wi = red_i[0];
                #pragma unroll
                for (int w = 1; w < 4; w++)
                    if (red_v[w] < wv) { wv = red_v[w]; wi = red_i[w]; }
                s_win = wi;
                idx_out[(b * Np + n) * Kn + it] = wi;
            }
            __syncthreads();
            int win = s_win;
            if ((win & 127) == t) {
                dist[win] = FLT_MAX;
                bestv = FLT_MAX; besti = t;
                #pragma unroll
                for (int i = 0; i < Np / 128; i++) {
                    int m = t + i * 128;
                    float fv = dist[m];
                    if (fv < bestv) { bestv = fv; besti = m; }
                }
            }
            __syncthreads();
        }
        __syncthreads();
    }
}

// ============================================================================
// Kernel 2a: per-POINT scale MLP (3 -> 64 -> 64 -> 128, relu).
// The MLP depends only on the point's coords, so evaluate once per unique
// point (16384 evals instead of 524288 gathered evals; identical fp32 math).
// grid (Jcols/128, 3 scales), block 128 threads (thread = one point).
// Output point-major: F[g][s*128+o], written coalesced via smem transpose.
// ============================================================================
__global__ __launch_bounds__(128) void scale_feat_kernel(
    const float* __restrict__ x, float* __restrict__ F,
    const float* __restrict__ sW0, const float* __restrict__ sb0,
    const float* __restrict__ sW1, const float* __restrict__ sb1,
    const float* __restrict__ sW2, const float* __restrict__ sb2) {
    extern __shared__ float sm[];
    float* w0 = sm;               // 192
    float* b0 = sm + 192;         // 64
    float* w1 = sm + 256;         // 4096
    float* b1 = sm + 4352;        // 64
    float* w2 = sm + 4416;        // 8192
    float* b2 = sm + 12608;       // 128
    float* stage = sm + 12736;    // 4 warps * 32 * 33

    const int t = threadIdx.x;
    const int s = blockIdx.y;
    for (int i = t; i < 192; i += 128)  w0[i] = sW0[s * 192 + i];
    for (int i = t; i < 64;  i += 128)  b0[i] = sb0[s * 64 + i];
    for (int i = t; i < 4096; i += 128) w1[i] = sW1[s * 4096 + i];
    for (int i = t; i < 64;  i += 128)  b1[i] = sb1[s * 64 + i];
    for (int i = t; i < 8192; i += 128) w2[i] = sW2[s * 8192 + i];
    for (int i = t; i < 128; i += 128)  b2[i] = sb2[s * 128 + i];
    __syncthreads();

    const int lane = t & 31;
    const int warp = t >> 5;
    const int g = blockIdx.x * 128 + t;        // global point id (b*Np+p)
    const int b = g >> 12;                     // Np = 4096
    const int p = g & (Np - 1);

    const float px = x[(b * 3 + 0) * Np + p];
    const float py = x[(b * 3 + 1) * Np + p];
    const float pz = x[(b * 3 + 2) * Np + p];

    float h0[64];
    #pragma unroll
    for (int o = 0; o < 64; o++) {
        float a = b0[o];
        a = fmaf(w0[o * 3 + 0], px, a);
        a = fmaf(w0[o * 3 + 1], py, a);
        a = fmaf(w0[o * 3 + 2], pz, a);
        h0[o] = fmaxf(a, 0.0f);
    }

    float h1[64];
    #pragma unroll
    for (int o = 0; o < 64; o++) {
        float a = b1[o];
        const float4* wr = (const float4*)&w1[o * 64];
        #pragma unroll
        for (int c = 0; c < 16; c++) {
            float4 wv = wr[c];
            a = fmaf(wv.x, h0[4 * c + 0], a);
            a = fmaf(wv.y, h0[4 * c + 1], a);
            a = fmaf(wv.z, h0[4 * c + 2], a);
            a = fmaf(wv.w, h0[4 * c + 3], a);
        }
        h1[o] = fmaxf(a, 0.0f);
    }

    float* st = stage + warp * (32 * 33);
    const int gbase = blockIdx.x * 128 + warp * 32;

    for (int chunk = 0; chunk < 4; chunk++) {
        for (int oo = 0; oo < 32; oo++) {
            const int o = chunk * 32 + oo;
            float a = b2[o];
            const float4* wr = (const float4*)&w2[o * 64];
            #pragma unroll
            for (int c = 0; c < 16; c++) {
                float4 wv = wr[c];
                a = fmaf(wv.x, h1[4 * c + 0], a);
                a = fmaf(wv.y, h1[4 * c + 1], a);
                a = fmaf(wv.z, h1[4 * c + 2], a);
                a = fmaf(wv.w, h1[4 * c + 3], a);
            }
            st[lane * 33 + oo] = fmaxf(a, 0.0f);   // row = my point, conflict-free
        }
        __syncwarp();
        #pragma unroll
        for (int pp = 0; pp < 32; pp++) {
            float v = st[pp * 33 + lane];
            F[(size_t)(gbase + pp) * 384 + s * 128 + chunk * 32 + lane] = v;
        }
        __syncwarp();
    }
}

// ============================================================================
// Kernel 2b: gather-max.  P0[col][bn] = max_k F[b*Np + idx[bn,k]][col].
// One warp per (b,n). Neighbor feature rows (1536 B) read fully coalesced
// (3 warp-wide LDG.128 per neighbor); 12 accumulators per lane.
// ============================================================================
__global__ __launch_bounds__(256) void gather_max_kernel(
    const int* __restrict__ idx, const float* __restrict__ F,
    float* __restrict__ P0) {
    const int w = (blockIdx.x * 256 + threadIdx.x) >> 5;  // bn in [0, 16384)
    const int lane = threadIdx.x & 31;
    const int base = (w >> 12) * Np;                      // batch offset

    int j = idx[w * Kn + lane];

    float4 a0 = make_float4(0.f, 0.f, 0.f, 0.f);          // relu outputs >= 0
    float4 a1 = a0, a2 = a0;

    #pragma unroll
    for (int k = 0; k < Kn; k++) {
        int jj = base + __shfl_sync(0xffffffffu, j, k);
        const float4* row = (const float4*)(F + (size_t)jj * 384);
        float4 v0 = row[lane];
        float4 v1 = row[lane + 32];
        float4 v2 = row[lane + 64];
        a0.x = fmaxf(a0.x, v0.x); a0.y = fmaxf(a0.y, v0.y);
        a0.z = fmaxf(a0.z, v0.z); a0.w = fmaxf(a0.w, v0.w);
        a1.x = fmaxf(a1.x, v1.x); a1.y = fmaxf(a1.y, v1.y);
        a1.z = fmaxf(a1.z, v1.z); a1.w = fmaxf(a1.w, v1.w);
        a2.x = fmaxf(a2.x, v2.x); a2.y = fmaxf(a2.y, v2.y);
        a2.z = fmaxf(a2.z, v2.z); a2.w = fmaxf(a2.w, v2.w);
    }

    const int c0 = 4 * lane;
    P0[(size_t)(c0 + 0) * Jcols + w] = a0.x;
    P0[(size_t)(c0 + 1) * Jcols + w] = a0.y;
    P0[(size_t)(c0 + 2) * Jcols + w] = a0.z;
    P0[(size_t)(c0 + 3) * Jcols + w] = a0.w;
    P0[(size_t)(128 + c0 + 0) * Jcols + w] = a1.x;
    P0[(size_t)(128 + c0 + 1) * Jcols + w] = a1.y;
    P0[(size_t)(128 + c0 + 2) * Jcols + w] = a1.z;
    P0[(size_t)(128 + c0 + 3) * Jcols + w] = a1.w;
    P0[(size_t)(256 + c0 + 0) * Jcols + w] = a2.x;
    P0[(size_t)(256 + c0 + 1) * Jcols + w] = a2.y;
    P0[(size_t)(256 + c0 + 2) * Jcols + w] = a2.z;
    P0[(size_t)(256 + c0 + 3) * Jcols + w] = a2.w;
}

// ============================================================================
// Kernel 3: SGEMM  Y[O][J] = relu(W[O][Cin] * X[Cin][J] + bias).
// 128x128 tile, BK=16, 256 threads, 8x8 microtile (two stride-64 groups of 4
// in each dim -> conflict-free LDS.128). 4 LDS.128 per 64 FFMA.
// mode 0: row-major Y. mode 1: msf layout Y[((j>>12)*128+o)*4096+(j&4095)].
// ============================================================================
__global__ __launch_bounds__(256) void gemm_relu_kernel(
    const float* __restrict__ W, const float* __restrict__ Bv,
    const float* __restrict__ X, float* __restrict__ Y,
    int O, int Cin, int mode) {
    __shared__ float Ws[16 * 132];   // [k][o], padded
    __shared__ float Xs[16 * 132];   // [k][j], padded

    const int t = threadIdx.x;
    const int o0 = blockIdx.y * 128, j0 = blockIdx.x * 128;

    const int lr = t >> 1;           // W: row within o-tile (0..127)
    const int lq = t & 1;            // W: which pair of k-chunks
    const int lk = t >> 4;           // X: k row (0..15)
    const int lj = t & 15;           // X: float4 col (0..15)

    const int tr = t >> 4;           // micro row group base (0..15)
    const int tc = t & 15;           // micro col group base (0..15)

    float acc[8][8];
    #pragma unroll
    for (int i = 0; i < 8; i++)
        #pragma unroll
        for (int jj = 0; jj < 8; jj++) acc[i][jj] = 0.0f;

    const float4* Ws4 = (const float4*)Ws;
    const float4* Xs4 = (const float4*)Xs;

    for (int k0 = 0; k0 < Cin; k0 += 16) {
        // load W tile (transpose to [k][o])
        #pragma unroll
        for (int h = 0; h < 2; h++) {
            const int c = lq + 2 * h;                 // k-chunk 0..3
            float4 wv = *(const float4*)&W[(size_t)(o0 + lr) * Cin + k0 + c * 4];
            Ws[(c * 4 + 0) * 132 + lr] = wv.x;
            Ws[(c * 4 + 1) * 132 + lr] = wv.y;
            Ws[(c * 4 + 2) * 132 + lr] = wv.z;
            Ws[(c * 4 + 3) * 132 + lr] = wv.w;
        }
        // load X tile
        #pragma unroll
        for (int h = 0; h < 2; h++) {
            float4 xv = *(const float4*)&X[(size_t)(k0 + lk) * Jcols + j0 + (lj + h * 16) * 4];
            *(float4*)&Xs[lk * 132 + (lj + h * 16) * 4] = xv;
        }
        __syncthreads();

        #pragma unroll
        for (int kk = 0; kk < 16; kk++) {
            float4 w0v = Ws4[kk * 33 + tr];
            float4 w1v = Ws4[kk * 33 + tr + 16];
            float4 x0v = Xs4[kk * 33 + tc];
            float4 x1v = Xs4[kk * 33 + tc + 16];
            float wa[8] = {w0v.x, w0v.y, w0v.z, w0v.w, w1v.x, w1v.y, w1v.z, w1v.w};
            float xb[8] = {x0v.x, x0v.y, x0v.z, x0v.w, x1v.x, x1v.y, x1v.z, x1v.w};
            #pragma unroll
            for (int i = 0; i < 8; i++)
                #pragma unroll
                for (int jj = 0; jj < 8; jj++)
                    acc[i][jj] = fmaf(wa[i], xb[jj], acc[i][jj]);
        }
        __syncthreads();
    }

    #pragma unroll
    for (int i = 0; i < 8; i++) {
        const int o = o0 + 4 * tr + ((i < 4) ? i : 60 + i);   // +64 group
        const float bi = Bv[o];
        #pragma unroll
        for (int gjj = 0; gjj < 2; gjj++) {
            const int jb = j0 + 4 * tc + gjj * 64;
            if (mode == 0) {
                float4 v;
                v.x = fmaxf(acc[i][gjj * 4 + 0] + bi, 0.0f);
                v.y = fmaxf(acc[i][gjj * 4 + 1] + bi, 0.0f);
                v.z = fmaxf(acc[i][gjj * 4 + 2] + bi, 0.0f);
                v.w = fmaxf(acc[i][gjj * 4 + 3] + bi, 0.0f);
                *(float4*)&Y[(size_t)o * Jcols + jb] = v;
            } else {
                #pragma unroll
                for (int jj = 0; jj < 4; jj++) {
                    const int j = jb + jj;
                    float v = fmaxf(acc[i][gjj * 4 + jj] + bi, 0.0f);
                    Y[(size_t)((j >> 12) * 128 + o) * Np + (j & (Np - 1))] = v;
                }
            }
        }
    }
}

// ============================================================================
// Kernel 4: global_feature[b][o] = max_n G2[o][b*Np+n].  One warp per (b,o).
// ============================================================================
__global__ __launch_bounds__(256) void gfmax_kernel(const float* __restrict__ G2,
                                                    float* __restrict__ out) {
    const int w = (blockIdx.x * blockDim.x + threadIdx.x) >> 5;
    const int lane = threadIdx.x & 31;
    const int b = w >> 10, o = w & 1023;
    const float* row = &G2[(size_t)o * Jcols + b * Np];
    float m = 0.0f;
    for (int i = lane; i < Np; i += 32) m = fmaxf(m, row[i]);
    #pragma unroll
    for (int off = 16; off; off >>= 1)
        m = fmaxf(m, __shfl_xor_sync(0xffffffffu, m, off));
    if (lane == 0) out[b * 1024 + o] = m;
}

// ============================================================================
extern "C" void kernel_launch(void* const* d_in, const int* in_sizes, int n_in,
                              void* d_out, int out_size) {
    const float* x   = (const float*)d_in[0];
    const float* sW0 = (const float*)d_in[1];
    const float* sb0 = (const float*)d_in[2];
    const float* sW1 = (const float*)d_in[3];
    const float* sb1 = (const float*)d_in[4];
    const float* sW2 = (const float*)d_in[5];
    const float* sb2 = (const float*)d_in[6];
    const float* gW0 = (const float*)d_in[7];
    const float* gb0 = (const float*)d_in[8];
    const float* gW1 = (const float*)d_in[9];
    const float* gb1 = (const float*)d_in[10];
    const float* mW0 = (const float*)d_in[11];
    const float* mb0 = (const float*)d_in[12];
    const float* mW1 = (const float*)d_in[13];
    const float* mb1 = (const float*)d_in[14];
    float* out = (float*)d_out;

    int* IDX; float *F, *P0, *G1, *G2, *M1;
    cudaGetSymbolAddress((void**)&IDX, g_idx);
    cudaGetSymbolAddress((void**)&F,  g_F);
    cudaGetSymbolAddress((void**)&P0, g_P0);
    cudaGetSymbolAddress((void**)&G1, g_G1);
    cudaGetSymbolAddress((void**)&G2, g_G2);
    cudaGetSymbolAddress((void**)&M1, g_M1);

    const int knn_smem  = 4 * Np * sizeof(float);                 // 64 KB
    const int feat_smem = (12736 + 4 * 32 * 33) * sizeof(float);  // ~66 KB
    cudaFuncSetAttribute(knn_kernel, cudaFuncAttributeMaxDynamicSharedMemorySize, knn_smem);
    cudaFuncSetAttribute(scale_feat_kernel, cudaFuncAttributeMaxDynamicSharedMemorySize, feat_smem);

    // 1) KNN
    knn_kernel<<<dim3(Np / QPB, Bq), 128, knn_smem>>>(x, IDX);

    // 2a) unique-point scale MLP -> F [16384][384] (point-major)
    scale_feat_kernel<<<dim3(Jcols / 128, 3), 128, feat_smem>>>(
        x, F, sW0, sb0, sW1, sb1, sW2, sb2);

    // 2b) gather + max over neighbors -> P0 [384][16384]
    gather_max_kernel<<<Jcols / 8, 256>>>(IDX, F, P0);

    // 3) dense chain
    gemm_relu_kernel<<<dim3(Jcols / 128, 256 / 128), 256>>>(gW0, gb0, P0, G1, 256, 384, 0);
    gemm_relu_kernel<<<dim3(Jcols / 128, 1024 / 128), 256>>>(gW1, gb1, G1, G2, 1024, 256, 0);

    // 4) global feature = max over N of G2 -> out[0 .. 4096)
    gfmax_kernel<<<512, 256>>>(G2, out);

    // 5) msf chain
    gemm_relu_kernel<<<dim3(Jcols / 128, 256 / 128), 256>>>(mW0, mb0, G2, M1, 256, 1024, 0);
    gemm_relu_kernel<<<dim3(Jcols / 128, 128 / 128), 256>>>(mW1, mb1, M1, out + Bq * 1024, 128, 256, 1);
}